// round 1
// baseline (speedup 1.0000x reference)
#include <cuda_runtime.h>
#include <cstdint>

// Problem constants (validated against in_sizes at launch)
#define N_NODES 50000
#define IN_CH   128
#define EDGE_DIM 32
#define CAT_CH  (IN_CH + EDGE_DIM)   // 160
#define OUT_CH  128

// 50000 * 160 floats = 32 MB scratch for the aggregated messages
__device__ __align__(128) float g_agg[(size_t)N_NODES * CAT_CH];

// ---------------------------------------------------------------------------
// Kernel 0: zero the scratch accumulator
// ---------------------------------------------------------------------------
__global__ void zero_kernel(int n_float4) {
    float4* p = reinterpret_cast<float4*>(g_agg);
    int i = blockIdx.x * blockDim.x + threadIdx.x;
    int stride = gridDim.x * blockDim.x;
    float4 z = make_float4(0.f, 0.f, 0.f, 0.f);
    for (; i < n_float4; i += stride) p[i] = z;
}

// ---------------------------------------------------------------------------
// Kernel 1: per-edge scatter.  One warp handles one edge.
//   agg[row] += norm * [ x[col] (128f) | edge_attr[e] (32f) ]
// x is 25.6MB -> L2 resident, agg is 32MB -> L2 resident; atomics resolve in L2.
// Uses red.global.add.v4.f32 (sm_90+) to quarter the atomic op count.
// ---------------------------------------------------------------------------
__device__ __forceinline__ void red_add_v4(float* dst, float a, float b, float c, float d) {
    asm volatile("red.global.add.v4.f32 [%0], {%1, %2, %3, %4};"
                 :: "l"(dst), "f"(a), "f"(b), "f"(c), "f"(d) : "memory");
}

__global__ void scatter_kernel(const float4* __restrict__ x4,       // [N, 32] float4
                               const int*    __restrict__ row,
                               const int*    __restrict__ col,
                               const float*  __restrict__ norm,
                               const float4* __restrict__ ea4,      // [E, 8] float4
                               int E) {
    int e    = (blockIdx.x * blockDim.x + threadIdx.x) >> 5;
    int lane = threadIdx.x & 31;
    if (e >= E) return;

    int   r  = __ldg(&row[e]);
    int   c  = __ldg(&col[e]);
    float nm = __ldg(&norm[e]);

    // 128-channel x message: 4 floats per lane
    float4 xv = __ldg(&x4[(size_t)c * (IN_CH / 4) + lane]);
    float* dst = g_agg + (size_t)r * CAT_CH + lane * 4;
    red_add_v4(dst, xv.x * nm, xv.y * nm, xv.z * nm, xv.w * nm);

    // 32-channel edge message: lanes 0..7
    if (lane < (EDGE_DIM / 4)) {
        float4 ev = __ldg(&ea4[(size_t)e * (EDGE_DIM / 4) + lane]);
        float* dste = g_agg + (size_t)r * CAT_CH + IN_CH + lane * 4;
        red_add_v4(dste, ev.x * nm, ev.y * nm, ev.z * nm, ev.w * nm);
    }
}

// ---------------------------------------------------------------------------
// Kernel 2: out[N,128] = agg[N,160] @ W[160,128] + b
// Block: 256 threads, 64-row tile. Thread computes 8 rows x 4 cols.
// Warp layout: lane = column-group -> W loads coalesced (float4),
// all lanes of a warp read the same agg smem word -> broadcast (no conflicts).
// ---------------------------------------------------------------------------
#define GEMM_ROWS 64

__global__ void gemm_kernel(const float* __restrict__ W,   // [160,128]
                            const float* __restrict__ b,   // [128]
                            float*       __restrict__ out, // [N,128]
                            int N) {
    __shared__ float sA[GEMM_ROWS][CAT_CH];   // 64*160*4 = 40 KB

    int tid = threadIdx.x;
    int rowBase = blockIdx.x * GEMM_ROWS;
    int nrows = N - rowBase;
    if (nrows > GEMM_ROWS) nrows = GEMM_ROWS;

    // Stage agg tile into shared memory (float4 loads)
    {
        const float4* aggv = reinterpret_cast<const float4*>(g_agg + (size_t)rowBase * CAT_CH);
        float4* sAv = reinterpret_cast<float4*>(&sA[0][0]);
        int nvec = nrows * (CAT_CH / 4);       // 40 float4 per row
        for (int i = tid; i < nvec; i += 256) sAv[i] = aggv[i];
    }
    __syncthreads();

    int cg = tid & 31;        // column group: cols cg*4 .. cg*4+3
    int rg = tid >> 5;        // row group:    rows rg*8 .. rg*8+7

    float acc[8][4];
    float4 bias = __ldg(reinterpret_cast<const float4*>(b) + cg);
    #pragma unroll
    for (int i = 0; i < 8; i++) {
        acc[i][0] = bias.x; acc[i][1] = bias.y; acc[i][2] = bias.z; acc[i][3] = bias.w;
    }

    #pragma unroll
    for (int k = 0; k < CAT_CH; k += 4) {
        float4 w0 = __ldg(reinterpret_cast<const float4*>(W + (size_t)(k + 0) * OUT_CH) + cg);
        float4 w1 = __ldg(reinterpret_cast<const float4*>(W + (size_t)(k + 1) * OUT_CH) + cg);
        float4 w2 = __ldg(reinterpret_cast<const float4*>(W + (size_t)(k + 2) * OUT_CH) + cg);
        float4 w3 = __ldg(reinterpret_cast<const float4*>(W + (size_t)(k + 3) * OUT_CH) + cg);
        #pragma unroll
        for (int i = 0; i < 8; i++) {
            float4 a = *reinterpret_cast<const float4*>(&sA[rg * 8 + i][k]);
            acc[i][0] += a.x * w0.x + a.y * w1.x + a.z * w2.x + a.w * w3.x;
            acc[i][1] += a.x * w0.y + a.y * w1.y + a.z * w2.y + a.w * w3.y;
            acc[i][2] += a.x * w0.z + a.y * w1.z + a.z * w2.z + a.w * w3.z;
            acc[i][3] += a.x * w0.w + a.y * w1.w + a.z * w2.w + a.w * w3.w;
        }
    }

    #pragma unroll
    for (int i = 0; i < 8; i++) {
        int r = rg * 8 + i;
        if (r < nrows) {
            float4 st = make_float4(acc[i][0], acc[i][1], acc[i][2], acc[i][3]);
            reinterpret_cast<float4*>(out + (size_t)(rowBase + r) * OUT_CH)[cg] = st;
        }
    }
}

// ---------------------------------------------------------------------------
// Launch
// ---------------------------------------------------------------------------
extern "C" void kernel_launch(void* const* d_in, const int* in_sizes, int n_in,
                              void* d_out, int out_size) {
    const float* x         = (const float*)d_in[0];  // [N,128]
    const int*   row       = (const int*)  d_in[1];  // [E]
    const int*   col       = (const int*)  d_in[2];  // [E]
    const float* norm      = (const float*)d_in[3];  // [E]
    const float* edge_attr = (const float*)d_in[4];  // [E,32]
    const float* W         = (const float*)d_in[5];  // [160,128]
    const float* b         = (const float*)d_in[6];  // [128]
    float* out = (float*)d_out;

    int N = in_sizes[0] / IN_CH;
    int E = in_sizes[1];

    // 0) zero accumulator
    {
        int n_f4 = (N * CAT_CH) / 4;
        int blocks = (n_f4 + 255) / 256;
        if (blocks > 8192) blocks = 8192;
        zero_kernel<<<blocks, 256>>>(n_f4);
    }

    // 1) scatter: one warp per edge
    {
        int warps_per_block = 8;                         // 256 threads
        int blocks = (E + warps_per_block - 1) / warps_per_block;
        scatter_kernel<<<blocks, warps_per_block * 32>>>(
            reinterpret_cast<const float4*>(x), row, col, norm,
            reinterpret_cast<const float4*>(edge_attr), E);
    }

    // 2) GEMM + bias
    {
        int blocks = (N + GEMM_ROWS - 1) / GEMM_ROWS;
        gemm_kernel<<<blocks, 256>>>(W, b, out, N);
    }
}

// round 2
// speedup vs baseline: 1.1137x; 1.1137x over previous
#include <cuda_runtime.h>
#include <cstdint>

#define N_NODES 50000
#define IN_CH   128
#define EDGE_DIM 32
#define CAT_CH  (IN_CH + EDGE_DIM)   // 160
#define OUT_CH  128
#define SCAN_THREADS 1024

// Static device scratch (no allocations allowed)
__device__ __align__(128) float g_agg[(size_t)N_NODES * CAT_CH];   // 32 MB
__device__ int g_count[N_NODES];
__device__ int g_start[N_NODES + 1];
__device__ int g_cursor[N_NODES];
__device__ int g_perm[1700000];                                    // >= E

// ---------------------------------------------------------------------------
// CSR build step 1: zero histogram
// ---------------------------------------------------------------------------
__global__ void zero_counts_kernel(int N) {
    int i = blockIdx.x * blockDim.x + threadIdx.x;
    if (i < N) g_count[i] = 0;
}

// step 2: histogram of row
__global__ void hist_kernel(const int* __restrict__ row, int E) {
    int i = blockIdx.x * blockDim.x + threadIdx.x;
    if (i < E) atomicAdd(&g_count[row[i]], 1);
}

// step 3: exclusive scan over 50K counts in a single 1024-thread block
__global__ void scan_kernel(int N) {
    __shared__ int ssum[SCAN_THREADS];
    const int CHUNK = (N_NODES + SCAN_THREADS - 1) / SCAN_THREADS;  // 49
    int t = threadIdx.x;
    int base = t * CHUNK;

    int local = 0;
    for (int i = 0; i < CHUNK; i++) {
        int idx = base + i;
        if (idx < N) local += g_count[idx];
    }
    ssum[t] = local;
    __syncthreads();

    // Hillis-Steele inclusive scan
    for (int off = 1; off < SCAN_THREADS; off <<= 1) {
        int v = 0;
        if (t >= off) v = ssum[t - off];
        __syncthreads();
        if (t >= off) ssum[t] += v;
        __syncthreads();
    }

    int running = (t == 0) ? 0 : ssum[t - 1];   // exclusive prefix for this chunk
    for (int i = 0; i < CHUNK; i++) {
        int idx = base + i;
        if (idx < N) {
            g_start[idx]  = running;
            g_cursor[idx] = running;
            running += g_count[idx];
        }
    }
    if (t == SCAN_THREADS - 1) g_start[N] = running;   // == E
}

// step 4: bucket fill -> permutation of edge ids grouped by row
__global__ void fill_kernel(const int* __restrict__ row, int E) {
    int i = blockIdx.x * blockDim.x + threadIdx.x;
    if (i < E) {
        int pos = atomicAdd(&g_cursor[row[i]], 1);
        g_perm[pos] = i;
    }
}

// ---------------------------------------------------------------------------
// Aggregation: one warp per node, register accumulation, NO output atomics.
//   agg[n] = sum over edges e with row[e]==n of norm[e] * [x[col[e]] | ea[e]]
// Lane l accumulates x-channels [4l,4l+4) (float4) and edge-channel l (scalar).
// Inner loop unrolled x4 for memory-level parallelism on the gather chain.
// ---------------------------------------------------------------------------
__global__ void aggregate_kernel(const float4* __restrict__ x4,    // [N,32] f4
                                 const int*    __restrict__ col,
                                 const float*  __restrict__ norm,
                                 const float*  __restrict__ ea,    // [E,32]
                                 int N) {
    int n    = (blockIdx.x * blockDim.x + threadIdx.x) >> 5;
    int lane = threadIdx.x & 31;
    if (n >= N) return;

    int s   = __ldg(&g_start[n]);
    int end = __ldg(&g_start[n + 1]);

    float4 acc = make_float4(0.f, 0.f, 0.f, 0.f);
    float  acce = 0.f;

    int j = s;
    for (; j + 4 <= end; j += 4) {
        int e0 = __ldg(&g_perm[j + 0]);
        int e1 = __ldg(&g_perm[j + 1]);
        int e2 = __ldg(&g_perm[j + 2]);
        int e3 = __ldg(&g_perm[j + 3]);
        int c0 = __ldg(&col[e0]), c1 = __ldg(&col[e1]);
        int c2 = __ldg(&col[e2]), c3 = __ldg(&col[e3]);
        float n0 = __ldg(&norm[e0]), n1 = __ldg(&norm[e1]);
        float n2 = __ldg(&norm[e2]), n3 = __ldg(&norm[e3]);

        float4 v0 = __ldg(&x4[(size_t)c0 * (IN_CH / 4) + lane]);
        float4 v1 = __ldg(&x4[(size_t)c1 * (IN_CH / 4) + lane]);
        float4 v2 = __ldg(&x4[(size_t)c2 * (IN_CH / 4) + lane]);
        float4 v3 = __ldg(&x4[(size_t)c3 * (IN_CH / 4) + lane]);
        float  g0 = __ldg(&ea[(size_t)e0 * EDGE_DIM + lane]);
        float  g1 = __ldg(&ea[(size_t)e1 * EDGE_DIM + lane]);
        float  g2 = __ldg(&ea[(size_t)e2 * EDGE_DIM + lane]);
        float  g3 = __ldg(&ea[(size_t)e3 * EDGE_DIM + lane]);

        acc.x += n0 * v0.x; acc.y += n0 * v0.y; acc.z += n0 * v0.z; acc.w += n0 * v0.w;
        acc.x += n1 * v1.x; acc.y += n1 * v1.y; acc.z += n1 * v1.z; acc.w += n1 * v1.w;
        acc.x += n2 * v2.x; acc.y += n2 * v2.y; acc.z += n2 * v2.z; acc.w += n2 * v2.w;
        acc.x += n3 * v3.x; acc.y += n3 * v3.y; acc.z += n3 * v3.z; acc.w += n3 * v3.w;
        acce += n0 * g0 + n1 * g1 + n2 * g2 + n3 * g3;
    }
    for (; j < end; j++) {
        int e = __ldg(&g_perm[j]);
        int c = __ldg(&col[e]);
        float nm = __ldg(&norm[e]);
        float4 v = __ldg(&x4[(size_t)c * (IN_CH / 4) + lane]);
        acc.x += nm * v.x; acc.y += nm * v.y; acc.z += nm * v.z; acc.w += nm * v.w;
        acce += nm * __ldg(&ea[(size_t)e * EDGE_DIM + lane]);
    }

    float* dst = g_agg + (size_t)n * CAT_CH;
    reinterpret_cast<float4*>(dst)[lane] = acc;
    dst[IN_CH + lane] = acce;
}

// ---------------------------------------------------------------------------
// GEMM: out[N,128] = agg[N,160] @ W[160,128] + b  (unchanged from R1)
// ---------------------------------------------------------------------------
#define GEMM_ROWS 64

__global__ void gemm_kernel(const float* __restrict__ W,
                            const float* __restrict__ b,
                            float*       __restrict__ out,
                            int N) {
    __shared__ float sA[GEMM_ROWS][CAT_CH];   // 40 KB

    int tid = threadIdx.x;
    int rowBase = blockIdx.x * GEMM_ROWS;
    int nrows = N - rowBase;
    if (nrows > GEMM_ROWS) nrows = GEMM_ROWS;

    {
        const float4* aggv = reinterpret_cast<const float4*>(g_agg + (size_t)rowBase * CAT_CH);
        float4* sAv = reinterpret_cast<float4*>(&sA[0][0]);
        int nvec = nrows * (CAT_CH / 4);
        for (int i = tid; i < nvec; i += 256) sAv[i] = aggv[i];
    }
    __syncthreads();

    int cg = tid & 31;
    int rg = tid >> 5;

    float acc[8][4];
    float4 bias = __ldg(reinterpret_cast<const float4*>(b) + cg);
    #pragma unroll
    for (int i = 0; i < 8; i++) {
        acc[i][0] = bias.x; acc[i][1] = bias.y; acc[i][2] = bias.z; acc[i][3] = bias.w;
    }

    #pragma unroll
    for (int k = 0; k < CAT_CH; k += 4) {
        float4 w0 = __ldg(reinterpret_cast<const float4*>(W + (size_t)(k + 0) * OUT_CH) + cg);
        float4 w1 = __ldg(reinterpret_cast<const float4*>(W + (size_t)(k + 1) * OUT_CH) + cg);
        float4 w2 = __ldg(reinterpret_cast<const float4*>(W + (size_t)(k + 2) * OUT_CH) + cg);
        float4 w3 = __ldg(reinterpret_cast<const float4*>(W + (size_t)(k + 3) * OUT_CH) + cg);
        #pragma unroll
        for (int i = 0; i < 8; i++) {
            float4 a = *reinterpret_cast<const float4*>(&sA[rg * 8 + i][k]);
            acc[i][0] += a.x * w0.x + a.y * w1.x + a.z * w2.x + a.w * w3.x;
            acc[i][1] += a.x * w0.y + a.y * w1.y + a.z * w2.y + a.w * w3.y;
            acc[i][2] += a.x * w0.z + a.y * w1.z + a.z * w2.z + a.w * w3.z;
            acc[i][3] += a.x * w0.w + a.y * w1.w + a.z * w2.w + a.w * w3.w;
        }
    }

    #pragma unroll
    for (int i = 0; i < 8; i++) {
        int r = rg * 8 + i;
        if (r < nrows) {
            float4 st = make_float4(acc[i][0], acc[i][1], acc[i][2], acc[i][3]);
            reinterpret_cast<float4*>(out + (size_t)(rowBase + r) * OUT_CH)[cg] = st;
        }
    }
}

// ---------------------------------------------------------------------------
// Launch
// ---------------------------------------------------------------------------
extern "C" void kernel_launch(void* const* d_in, const int* in_sizes, int n_in,
                              void* d_out, int out_size) {
    const float* x         = (const float*)d_in[0];
    const int*   row       = (const int*)  d_in[1];
    const int*   col       = (const int*)  d_in[2];
    const float* norm      = (const float*)d_in[3];
    const float* edge_attr = (const float*)d_in[4];
    const float* W         = (const float*)d_in[5];
    const float* b         = (const float*)d_in[6];
    float* out = (float*)d_out;

    int N = in_sizes[0] / IN_CH;
    int E = in_sizes[1];

    // CSR build
    zero_counts_kernel<<<(N + 255) / 256, 256>>>(N);
    hist_kernel<<<(E + 255) / 256, 256>>>(row, E);
    scan_kernel<<<1, SCAN_THREADS>>>(N);
    fill_kernel<<<(E + 255) / 256, 256>>>(row, E);

    // Per-node register aggregation (one warp per node)
    {
        int warps_per_block = 8;   // 256 threads
        int blocks = (N + warps_per_block - 1) / warps_per_block;
        aggregate_kernel<<<blocks, warps_per_block * 32>>>(
            reinterpret_cast<const float4*>(x), col, norm, edge_attr, N);
    }

    // GEMM + bias
    gemm_kernel<<<(N + GEMM_ROWS - 1) / GEMM_ROWS, 256>>>(W, b, out, N);
}